// round 13
// baseline (speedup 1.0000x reference)
#include <cuda_runtime.h>
#include <math.h>
#include <stdint.h>

#define T_SEQ 2048
#define B_SZ  2
#define C_DIM 1024
#define H_NUM 16
#define D_HEAD 64
#define M_ROWS (T_SEQ * B_SZ)   // 4096

// Q: pre-scaled (x 0.125*log2e), tf32-rounded, column-permuted (groups of 8)
// K: tf32-rounded, column-permuted
// V: tf32-rounded, TRANSPOSED (b,h,d,t) with t-permuted within groups of 8
__device__ float g_q[(size_t)B_SZ * H_NUM * T_SEQ * D_HEAD];
__device__ float g_k[(size_t)B_SZ * H_NUM * T_SEQ * D_HEAD];
__device__ float g_v[(size_t)B_SZ * H_NUM * T_SEQ * D_HEAD];
__device__ float g_xc[(size_t)M_ROWS * C_DIM];        // x, tf32-rounded, permuted cols
__device__ float g_wc[4][(size_t)C_DIM * C_DIM];      // Wq,Wk,Wv,Wo rounded+permuted
__device__ float g_ctxp[(size_t)M_ROWS * C_DIM];      // ctx, rounded+permuted

#define QSCALE 0.18033688f   // 0.125 * log2(e)

__device__ __forceinline__ float cvt_tf32(float x) {
    uint32_t r;
    asm("cvt.rna.tf32.f32 %0, %1;" : "=r"(r) : "f"(x));
    return __uint_as_float(r);
}

__device__ __forceinline__ float ex2f(float x) {
    float r;
    asm("ex2.approx.f32 %0, %1;" : "=f"(r) : "f"(x));
    return r;
}

__device__ __forceinline__ void mma_tf32(float c[4], const uint32_t a[4],
                                         uint32_t b0, uint32_t b1) {
    asm volatile(
        "mma.sync.aligned.m16n8k8.row.col.f32.tf32.tf32.f32 "
        "{%0,%1,%2,%3}, {%4,%5,%6,%7}, {%8,%9}, {%0,%1,%2,%3};"
        : "+f"(c[0]), "+f"(c[1]), "+f"(c[2]), "+f"(c[3])
        : "r"(a[0]), "r"(a[1]), "r"(a[2]), "r"(a[3]), "r"(b0), "r"(b1));
}

#define CP16(dst_u32, src_ptr) \
    asm volatile("cp.async.cg.shared.global [%0], [%1], 16;" \
                 :: "r"(dst_u32), "l"(src_ptr))
#define CP_COMMIT() asm volatile("cp.async.commit_group;" ::: "memory")
#define CP_WAIT0()  asm volatile("cp.async.wait_group 0;" ::: "memory")
#define CP_WAIT1()  asm volatile("cp.async.wait_group 1;" ::: "memory")

// ---------------------------------------------------------------------------
// Pre-convert: round to tf32 and permute columns within groups of 8:
//   pos(k) = (k & ~7) | ((k & 3) << 1) | ((k >> 2) & 1)
// ---------------------------------------------------------------------------
#define X_F4 (M_ROWS * C_DIM / 4)   // 1048576
#define W_F4 (C_DIM * C_DIM / 4)    // 262144

__global__ __launch_bounds__(256) void preconvert_kernel(
    const float* __restrict__ x,  const float* __restrict__ Wq,
    const float* __restrict__ Wk, const float* __restrict__ Wv,
    const float* __restrict__ Wo)
{
    int g = blockIdx.x * 256 + threadIdx.x;
    const float* src;
    float* dst;
    int off;
    if (g < X_F4) {
        src = x; dst = g_xc; off = g;
    } else {
        int r = g - X_F4;
        int t = r / W_F4;
        off = r - t * W_F4;
        src = (t == 0) ? Wq : (t == 1) ? Wk : (t == 2) ? Wv : Wo;
        dst = g_wc[t];
    }
    float4 v = ((const float4*)src)[off];
    int fi   = off * 4;
    int col4 = fi & (C_DIM - 1);
    int rowb = fi - col4;
    int pb   = (col4 & ~7) + ((col4 >> 2) & 1);
    dst[rowb + pb    ] = cvt_tf32(v.x);
    dst[rowb + pb + 2] = cvt_tf32(v.y);
    dst[rowb + pb + 4] = cvt_tf32(v.z);
    dst[rowb + pb + 6] = cvt_tf32(v.w);
}

// ---------------------------------------------------------------------------
// TF32 NT GEMM (round-8/11 config): CTA 128x128, BK=32, 256 threads (8 warps
// 2x4), warp 64x32, SPAD=40, 2-stage cp.async, LDS.64-only mainloop.
// ---------------------------------------------------------------------------
#define BM 128
#define BN 128
#define BK 32
#define SPAD 40
#define STAGE_F (BM * SPAD)                 // 5120 floats
#define GEMM_SMEM (2 * 2 * STAGE_F * 4)     // 81920 bytes

__device__ __forceinline__ void issue_stage(uint32_t s_a, uint32_t s_b,
                                            const float* __restrict__ A,
                                            const float* __restrict__ W,
                                            int bm, int bn, int k0, int tid) {
    const int row0 = tid >> 3;           // 0..31
    const int c4   = (tid & 7) * 4;      // 0..28
    #pragma unroll
    for (int i = 0; i < 4; i++) {
        int r = row0 + i * 32;
        uint32_t d = s_a + (uint32_t)((r * SPAD + c4) * 4);
        CP16(d, A + (size_t)(bm + r) * C_DIM + k0 + c4);
    }
    #pragma unroll
    for (int i = 0; i < 4; i++) {
        int r = row0 + i * 32;
        uint32_t d = s_b + (uint32_t)((r * SPAD + c4) * 4);
        CP16(d, W + (size_t)(bn + r) * C_DIM + k0 + c4);
    }
}

__device__ __forceinline__ void tile_mma4(const float* __restrict__ As,
                                          const float* __restrict__ Bs,
                                          float c[4][4][4],
                                          int wm, int wn, int gid, int tig) {
    #pragma unroll
    for (int kk = 0; kk < 4; kk++) {
        const int k2 = kk * 8 + tig * 2;   // permuted col of (k, k+4) pair
        uint32_t a[4][4];
        #pragma unroll
        for (int mt = 0; mt < 4; mt++) {
            int r = wm * 64 + mt * 16 + gid;
            float2 f0 = *(const float2*)&As[(size_t)r * SPAD + k2];
            float2 f1 = *(const float2*)&As[(size_t)(r + 8) * SPAD + k2];
            a[mt][0] = __float_as_uint(f0.x);
            a[mt][1] = __float_as_uint(f1.x);
            a[mt][2] = __float_as_uint(f0.y);
            a[mt][3] = __float_as_uint(f1.y);
        }
        #pragma unroll
        for (int nt = 0; nt < 4; nt++) {
            int cn = wn * 32 + nt * 8 + gid;
            float2 fb = *(const float2*)&Bs[(size_t)cn * SPAD + k2];
            #pragma unroll
            for (int mt = 0; mt < 4; mt++)
                mma_tf32(c[mt][nt], a[mt],
                         __float_as_uint(fb.x), __float_as_uint(fb.y));
        }
    }
}

__device__ __forceinline__ void gemm_mainloop(const float* __restrict__ A,
                                              const float* __restrict__ W,
                                              float c[4][4][4],
                                              int bm, int bn, int tid) {
    extern __shared__ float dyn[];
    uint32_t sbase;
    asm("{ .reg .u64 t; cvta.to.shared.u64 t, %1; cvt.u32.u64 %0, t; }"
        : "=r"(sbase) : "l"(dyn));

    const int lane = tid & 31, wid = tid >> 5;
    const int gid = lane >> 2, tig = lane & 3;
    const int wm = wid >> 2, wn = wid & 3;

    const int NIT = C_DIM / BK;   // 32

    issue_stage(sbase, sbase + (uint32_t)(STAGE_F * 4), A, W, bm, bn, 0, tid);
    CP_COMMIT();

    for (int i = 0; i < NIT; i++) {
        CP_WAIT0();
        __syncthreads();

        int nxt = i + 1;
        if (nxt < NIT) {
            uint32_t s_a = sbase + (uint32_t)((nxt & 1) * 2 * STAGE_F * 4);
            uint32_t s_b = s_a + (uint32_t)(STAGE_F * 4);
            issue_stage(s_a, s_b, A, W, bm, bn, nxt * BK, tid);
        }
        CP_COMMIT();

        const float* As = dyn + (size_t)(i & 1) * 2 * STAGE_F;
        const float* Bs = As + STAGE_F;
        tile_mma4(As, Bs, c, wm, wn, gid, tig);
    }
}

// QKV fused. Epilogue: Q scaled(0.125*log2e)+rounded+permuted, K rounded+
// permuted, V rounded TRANSPOSED (b,h,d,t) with permuted t.
__global__ __launch_bounds__(256, 2) void gemm_qkv_kernel()
{
    const int z = blockIdx.z;
    const float* W = g_wc[z];

    const int tid = threadIdx.x;
    const int lane = tid & 31, wid = tid >> 5;
    const int gid = lane >> 2, tig = lane & 3;
    const int wm = wid >> 2, wn = wid & 3;
    const int bm = blockIdx.y * BM, bn = blockIdx.x * BN;

    float c[4][4][4];
    #pragma unroll
    for (int mt = 0; mt < 4; mt++)
        #pragma unroll
        for (int nt = 0; nt < 4; nt++)
            #pragma unroll
            for (int i = 0; i < 4; i++) c[mt][nt][i] = 0.f;

    gemm_mainloop(g_xc, W, c, bm, bn, tid);

    #pragma unroll
    for (int mt = 0; mt < 4; mt++)
        #pragma unroll
        for (int nt = 0; nt < 4; nt++) {
            int row0 = bm + wm * 64 + mt * 16 + gid;
            int n    = bn + wn * 32 + nt * 8 + tig * 2;
            int hh = n >> 6, d = n & 63;
            if (z <= 1) {
                float* dst = (z == 0) ? g_q : g_k;
                const float scale = (z == 0) ? QSCALE : 1.0f;
                int dp = (d & ~7) | ((d & 3) << 1) | ((d >> 2) & 1);
                #pragma unroll
                for (int i = 0; i < 2; i++) {
                    int m = row0 + i * 8;
                    int t = m >> 1, bb = m & 1;
                    size_t base = (((size_t)bb * H_NUM + hh) * T_SEQ + t) * D_HEAD;
                    dst[base + dp    ] = cvt_tf32(c[mt][nt][i * 2    ] * scale);
                    dst[base + dp + 2] = cvt_tf32(c[mt][nt][i * 2 + 1] * scale);
                }
            } else {
                // V transposed: g_v[((bb*H+hh)*D + d) * T + perm(t)]
                #pragma unroll
                for (int i = 0; i < 2; i++) {
                    int m = row0 + i * 8;
                    int t = m >> 1, bb = m & 1;
                    int tp = (t & ~7) | ((t & 3) << 1) | ((t >> 2) & 1);
                    size_t vb = (((size_t)bb * H_NUM + hh) * D_HEAD + d) * T_SEQ + tp;
                    g_v[vb        ] = cvt_tf32(c[mt][nt][i * 2]);
                    g_v[vb + T_SEQ] = cvt_tf32(c[mt][nt][i * 2 + 1]);   // d+1
                }
            }
        }
}

__global__ __launch_bounds__(256, 2) void gemm_out_kernel(float* __restrict__ out)
{
    const int tid = threadIdx.x;
    const int lane = tid & 31, wid = tid >> 5;
    const int gid = lane >> 2, tig = lane & 3;
    const int wm = wid >> 2, wn = wid & 3;
    const int bm = blockIdx.y * BM, bn = blockIdx.x * BN;

    float c[4][4][4];
    #pragma unroll
    for (int mt = 0; mt < 4; mt++)
        #pragma unroll
        for (int nt = 0; nt < 4; nt++)
            #pragma unroll
            for (int i = 0; i < 4; i++) c[mt][nt][i] = 0.f;

    gemm_mainloop(g_ctxp, g_wc[3], c, bm, bn, tid);

    #pragma unroll
    for (int mt = 0; mt < 4; mt++)
        #pragma unroll
        for (int nt = 0; nt < 4; nt++) {
            int row0 = bm + wm * 64 + mt * 16 + gid;
            int col0 = bn + wn * 32 + nt * 8 + tig * 2;
            *(float2*)(out + (size_t)row0 * C_DIM + col0) =
                make_float2(c[mt][nt][0], c[mt][nt][1]);
            *(float2*)(out + (size_t)(row0 + 8) * C_DIM + col0) =
                make_float2(c[mt][nt][2], c[mt][nt][3]);
        }
}

// ---------------------------------------------------------------------------
// Tensor-core causal flash attention v5: log2-domain softmax (ex2.approx),
// V transposed+permuted -> PV b-frags are LDS.64 like K. cp.async double-
// buffered K/V staging, zero cvt in the loop. 128 threads = 4 warps.
// ---------------------------------------------------------------------------
#define AT_TILE (64 * 72)
#define AT_STAGE (2 * AT_TILE)
#define ATTN_SMEM (2 * AT_STAGE * 4)

__device__ __forceinline__ void attn_issue_kv(uint32_t sbase, int stage,
                                              const float* __restrict__ Kp,
                                              const float* __restrict__ Vp,
                                              int kb, int tid) {
    uint32_t kdst = sbase + (uint32_t)(stage * AT_STAGE * 4);
    uint32_t vdst = kdst + (uint32_t)(AT_TILE * 4);
    #pragma unroll
    for (int it = 0; it < 8; it++) {
        int idx = tid + it * 128;
        int r  = idx >> 4;             // 0..63
        int cc = (idx & 15) * 4;       // 0..60
        uint32_t off = (uint32_t)((r * 72 + cc) * 4);
        // K: row r = kv position, cols = head dim (permuted in gmem)
        CP16(kdst + off, Kp + (size_t)(kb * 64 + r) * 64 + cc);
        // V^T: row r = head dim, cols = kv position (permuted in gmem)
        CP16(vdst + off, Vp + (size_t)r * T_SEQ + kb * 64 + cc);
    }
}

__global__ __launch_bounds__(128) void attn_tc_kernel()
{
    const int qb = (gridDim.x - 1) - blockIdx.x;
    const int h  = blockIdx.y;
    const int b  = blockIdx.z;
    const size_t base = (((size_t)b * H_NUM + h) * T_SEQ) * D_HEAD;
    const float* Qp = g_q + base;
    const float* Kp = g_k + base;
    const float* Vp = g_v + base;   // transposed layout, same base offset

    extern __shared__ float at_dyn[];
    uint32_t sbase;
    asm("{ .reg .u64 t; cvta.to.shared.u64 t, %1; cvt.u32.u64 %0, t; }"
        : "=r"(sbase) : "l"(at_dyn));

    const int tid  = threadIdx.x;
    const int lane = tid & 31;
    const int wid  = tid >> 5;
    const int gid  = lane >> 2;
    const int tig  = lane & 3;

    const int t0 = qb * 64 + wid * 16 + gid;
    const int t1 = t0 + 8;

    uint32_t qa[8][4];
    #pragma unroll
    for (int kk = 0; kk < 8; kk++) {
        float2 f0 = *(const float2*)(Qp + (size_t)t0 * 64 + kk * 8 + tig * 2);
        float2 f1 = *(const float2*)(Qp + (size_t)t1 * 64 + kk * 8 + tig * 2);
        qa[kk][0] = __float_as_uint(f0.x);
        qa[kk][1] = __float_as_uint(f1.x);
        qa[kk][2] = __float_as_uint(f0.y);
        qa[kk][3] = __float_as_uint(f1.y);
    }

    float m0 = -1e30f, m1 = -1e30f, l0 = 0.f, l1 = 0.f;
    float o[8][4];
    #pragma unroll
    for (int nt = 0; nt < 8; nt++)
        #pragma unroll
        for (int i = 0; i < 4; i++) o[nt][i] = 0.f;

    const int nkb = qb + 1;

    attn_issue_kv(sbase, 0, Kp, Vp, 0, tid);
    CP_COMMIT();

    for (int kb = 0; kb < nkb; kb++) {
        if (kb + 1 < nkb) {
            attn_issue_kv(sbase, (kb + 1) & 1, Kp, Vp, kb + 1, tid);
            CP_COMMIT();
            CP_WAIT1();
        } else {
            CP_WAIT0();
        }
        __syncthreads();

        const float* Ks = at_dyn + (size_t)(kb & 1) * AT_STAGE;
        const float* Vs = Ks + AT_TILE;

        float s[8][4];
        #pragma unroll
        for (int nt = 0; nt < 8; nt++)
            #pragma unroll
            for (int i = 0; i < 4; i++) s[nt][i] = 0.f;

        #pragma unroll
        for (int kk = 0; kk < 8; kk++) {
            #pragma unroll
            for (int nt = 0; nt < 8; nt++) {
                float2 kbf = *(const float2*)&Ks[(size_t)(nt * 8 + gid) * 72 + kk * 8 + tig * 2];
                mma_tf32(s[nt], qa[kk], __float_as_uint(kbf.x), __float_as_uint(kbf.y));
            }
        }

        if (kb == qb) {
            #pragma unroll
            for (int nt = 0; nt < 8; nt++) {
                int cg = kb * 64 + nt * 8 + tig * 2;
                if (cg     > t0) s[nt][0] = -1e30f;
                if (cg + 1 > t0) s[nt][1] = -1e30f;
                if (cg     > t1) s[nt][2] = -1e30f;
                if (cg + 1 > t1) s[nt][3] = -1e30f;
            }
        }

        float mb0 = m0, mb1 = m1;
        #pragma unroll
        for (int nt = 0; nt < 8; nt++) {
            mb0 = fmaxf(mb0, fmaxf(s[nt][0], s[nt][1]));
            mb1 = fmaxf(mb1, fmaxf(s[nt][2], s[nt][3]));
        }
        mb0 = fmaxf(mb0, __shfl_xor_sync(0xffffffffu, mb0, 1));
        mb0 = fmaxf(mb0, __shfl_xor_sync(0xffffffffu, mb0, 2));
        mb1 = fmaxf(mb1, __shfl_xor_sync(0xffffffffu, mb1, 1));
        mb1 = fmaxf(mb1, __shfl_xor_sync(0xffffffffu, mb1, 2));

        // log2-domain corrections: one MUFU each
        float corr0 = ex2f(m0 - mb0);
        float corr1 = ex2f(m1 - mb1);
        m0 = mb0; m1 = mb1;
        l0 *= corr0; l1 *= corr1;
        #pragma unroll
        for (int nt = 0; nt < 8; nt++) {
            o[nt][0] *= corr0; o[nt][1] *= corr0;
            o[nt][2] *= corr1; o[nt][3] *= corr1;
        }

        #pragma unroll
        for (int nt = 0; nt < 8; nt++) {
            s[nt][0] = ex2f(s[nt][0] - m0);
            s[nt][1] = ex2f(s[nt][1] - m0);
            s[nt][2] = ex2f(s[nt][2] - m1);
            s[nt][3] = ex2f(s[nt][3] - m1);
            l0 += s[nt][0] + s[nt][1];
            l1 += s[nt][2] + s[nt][3];
        }

        #pragma unroll
        for (int kk = 0; kk < 8; kk++) {
            int src  = (lane & ~3) | (tig >> 1);
            int src2 = src + 2;
            float v00 = __shfl_sync(0xffffffffu, s[kk][0], src);
            float v01 = __shfl_sync(0xffffffffu, s[kk][1], src);
            float v10 = __shfl_sync(0xffffffffu, s[kk][2], src);
            float v11 = __shfl_sync(0xffffffffu, s[kk][3], src);
            float w00 = __shfl_sync(0xffffffffu, s[kk][0], src2);
            float w01 = __shfl_sync(0xffffffffu, s[kk][1], src2);
            float w10 = __shfl_sync(0xffffffffu, s[kk][2], src2);
            float w11 = __shfl_sync(0xffffffffu, s[kk][3], src2);
            bool odd = (tig & 1);
            uint32_t pa[4];
            pa[0] = __float_as_uint(cvt_tf32(odd ? v01 : v00));
            pa[1] = __float_as_uint(cvt_tf32(odd ? v11 : v10));
            pa[2] = __float_as_uint(cvt_tf32(odd ? w01 : w00));
            pa[3] = __float_as_uint(cvt_tf32(odd ? w11 : w10));
            #pragma unroll
            for (int nt = 0; nt < 8; nt++) {
                // V^T rows = head dim, cols = kv (permuted) -> LDS.64
                float2 vbf = *(const float2*)&Vs[(size_t)(nt * 8 + gid) * 72 + kk * 8 + tig * 2];
                mma_tf32(o[nt], pa, __float_as_uint(vbf.x), __float_as_uint(vbf.y));
            }
        }
        __syncthreads();
    }

    l0 += __shfl_xor_sync(0xffffffffu, l0, 1);
    l0 += __shfl_xor_sync(0xffffffffu, l0, 2);
    l1 += __shfl_xor_sync(0xffffffffu, l1, 1);
    l1 += __shfl_xor_sync(0xffffffffu, l1, 2);
    float inv0 = 1.f / l0;
    float inv1 = 1.f / l1;

    // ctx: rounded + column-permuted (groups of 8) for the mma.sync out-proj
    const int k0 = tig * 2;
    const int p0 = ((k0 & 3) << 1) | ((k0 >> 2) & 1);
    const int p1 = (((k0 + 1) & 3) << 1) | (((k0 + 1) >> 2) & 1);
    #pragma unroll
    for (int nt = 0; nt < 8; nt++) {
        int cb = h * 64 + nt * 8;
        size_t r0 = ((size_t)t0 * B_SZ + b) * C_DIM + cb;
        size_t r1 = ((size_t)t1 * B_SZ + b) * C_DIM + cb;
        g_ctxp[r0 + p0] = cvt_tf32(o[nt][0] * inv0);
        g_ctxp[r0 + p1] = cvt_tf32(o[nt][1] * inv0);
        g_ctxp[r1 + p0] = cvt_tf32(o[nt][2] * inv1);
        g_ctxp[r1 + p1] = cvt_tf32(o[nt][3] * inv1);
    }
}

// ---------------------------------------------------------------------------
extern "C" void kernel_launch(void* const* d_in, const int* in_sizes, int n_in,
                              void* d_out, int out_size)
{
    const float* x  = (const float*)d_in[0];
    const float* Wq = (const float*)d_in[1];
    const float* Wk = (const float*)d_in[2];
    const float* Wv = (const float*)d_in[3];
    const float* Wo = (const float*)d_in[4];
    float* out = (float*)d_out;

    cudaFuncSetAttribute(gemm_qkv_kernel,
                         cudaFuncAttributeMaxDynamicSharedMemorySize, GEMM_SMEM);
    cudaFuncSetAttribute(gemm_out_kernel,
                         cudaFuncAttributeMaxDynamicSharedMemorySize, GEMM_SMEM);
    cudaFuncSetAttribute(attn_tc_kernel,
                         cudaFuncAttributeMaxDynamicSharedMemorySize, ATTN_SMEM);

    int nconv = (X_F4 + 4 * W_F4) / 256;     // 8192 blocks
    preconvert_kernel<<<nconv, 256>>>(x, Wq, Wk, Wv, Wo);

    dim3 gq(C_DIM / BN, M_ROWS / BM, 3);     // (8, 32, 3)
    gemm_qkv_kernel<<<gq, 256, GEMM_SMEM>>>();

    dim3 ga(T_SEQ / 64, H_NUM, B_SZ);        // (32, 16, 2)
    attn_tc_kernel<<<ga, 128, ATTN_SMEM>>>();

    dim3 go(C_DIM / BN, M_ROWS / BM);        // (8, 32)
    gemm_out_kernel<<<go, 256, GEMM_SMEM>>>(out);
}

// round 14
// speedup vs baseline: 1.1142x; 1.1142x over previous
#include <cuda_runtime.h>
#include <math.h>
#include <stdint.h>

#define T_SEQ 2048
#define B_SZ  2
#define C_DIM 1024
#define H_NUM 16
#define D_HEAD 64
#define M_ROWS (T_SEQ * B_SZ)   // 4096

// Q: pre-scaled (x 0.125*log2e), tf32-rounded, column-permuted (groups of 8)
// K: tf32-rounded, column-permuted
// V: tf32-rounded, natural layout
__device__ float g_q[(size_t)B_SZ * H_NUM * T_SEQ * D_HEAD];
__device__ float g_k[(size_t)B_SZ * H_NUM * T_SEQ * D_HEAD];
__device__ float g_v[(size_t)B_SZ * H_NUM * T_SEQ * D_HEAD];
__device__ float g_xc[(size_t)M_ROWS * C_DIM];        // x, tf32-rounded, permuted cols
__device__ float g_wc[4][(size_t)C_DIM * C_DIM];      // Wq,Wk,Wv,Wo rounded+permuted
__device__ float g_ctxp[(size_t)M_ROWS * C_DIM];      // ctx, rounded+permuted

#define QSCALE 0.18033688f   // 0.125 * log2(e)

__device__ __forceinline__ float cvt_tf32(float x) {
    uint32_t r;
    asm("cvt.rna.tf32.f32 %0, %1;" : "=r"(r) : "f"(x));
    return __uint_as_float(r);
}

__device__ __forceinline__ float ex2f(float x) {
    float r;
    asm("ex2.approx.f32 %0, %1;" : "=f"(r) : "f"(x));
    return r;
}

__device__ __forceinline__ void mma_tf32(float c[4], const uint32_t a[4],
                                         uint32_t b0, uint32_t b1) {
    asm volatile(
        "mma.sync.aligned.m16n8k8.row.col.f32.tf32.tf32.f32 "
        "{%0,%1,%2,%3}, {%4,%5,%6,%7}, {%8,%9}, {%0,%1,%2,%3};"
        : "+f"(c[0]), "+f"(c[1]), "+f"(c[2]), "+f"(c[3])
        : "r"(a[0]), "r"(a[1]), "r"(a[2]), "r"(a[3]), "r"(b0), "r"(b1));
}

#define CP16(dst_u32, src_ptr) \
    asm volatile("cp.async.cg.shared.global [%0], [%1], 16;" \
                 :: "r"(dst_u32), "l"(src_ptr))
#define CP_COMMIT() asm volatile("cp.async.commit_group;" ::: "memory")
#define CP_WAIT0()  asm volatile("cp.async.wait_group 0;" ::: "memory")
#define CP_WAIT1()  asm volatile("cp.async.wait_group 1;" ::: "memory")

// ---------------------------------------------------------------------------
// Pre-convert: round to tf32 and permute columns within groups of 8:
//   pos(k) = (k & ~7) | ((k & 3) << 1) | ((k >> 2) & 1)
// ---------------------------------------------------------------------------
#define X_F4 (M_ROWS * C_DIM / 4)   // 1048576
#define W_F4 (C_DIM * C_DIM / 4)    // 262144

__global__ __launch_bounds__(256) void preconvert_kernel(
    const float* __restrict__ x,  const float* __restrict__ Wq,
    const float* __restrict__ Wk, const float* __restrict__ Wv,
    const float* __restrict__ Wo)
{
    int g = blockIdx.x * 256 + threadIdx.x;
    const float* src;
    float* dst;
    int off;
    if (g < X_F4) {
        src = x; dst = g_xc; off = g;
    } else {
        int r = g - X_F4;
        int t = r / W_F4;
        off = r - t * W_F4;
        src = (t == 0) ? Wq : (t == 1) ? Wk : (t == 2) ? Wv : Wo;
        dst = g_wc[t];
    }
    float4 v = ((const float4*)src)[off];
    int fi   = off * 4;
    int col4 = fi & (C_DIM - 1);
    int rowb = fi - col4;
    int pb   = (col4 & ~7) + ((col4 >> 2) & 1);
    dst[rowb + pb    ] = cvt_tf32(v.x);
    dst[rowb + pb + 2] = cvt_tf32(v.y);
    dst[rowb + pb + 4] = cvt_tf32(v.z);
    dst[rowb + pb + 6] = cvt_tf32(v.w);
}

// ---------------------------------------------------------------------------
// TF32 NT GEMM (round-8/11 config): CTA 128x128, BK=32, 256 threads (8 warps
// 2x4), warp 64x32, SPAD=40, 2-stage cp.async, LDS.64-only mainloop.
// ---------------------------------------------------------------------------
#define BM 128
#define BN 128
#define BK 32
#define SPAD 40
#define STAGE_F (BM * SPAD)                 // 5120 floats
#define GEMM_SMEM (2 * 2 * STAGE_F * 4)     // 81920 bytes

__device__ __forceinline__ void issue_stage(uint32_t s_a, uint32_t s_b,
                                            const float* __restrict__ A,
                                            const float* __restrict__ W,
                                            int bm, int bn, int k0, int tid) {
    const int row0 = tid >> 3;           // 0..31
    const int c4   = (tid & 7) * 4;      // 0..28
    #pragma unroll
    for (int i = 0; i < 4; i++) {
        int r = row0 + i * 32;
        uint32_t d = s_a + (uint32_t)((r * SPAD + c4) * 4);
        CP16(d, A + (size_t)(bm + r) * C_DIM + k0 + c4);
    }
    #pragma unroll
    for (int i = 0; i < 4; i++) {
        int r = row0 + i * 32;
        uint32_t d = s_b + (uint32_t)((r * SPAD + c4) * 4);
        CP16(d, W + (size_t)(bn + r) * C_DIM + k0 + c4);
    }
}

__device__ __forceinline__ void tile_mma4(const float* __restrict__ As,
                                          const float* __restrict__ Bs,
                                          float c[4][4][4],
                                          int wm, int wn, int gid, int tig) {
    #pragma unroll
    for (int kk = 0; kk < 4; kk++) {
        const int k2 = kk * 8 + tig * 2;   // permuted col of (k, k+4) pair
        uint32_t a[4][4];
        #pragma unroll
        for (int mt = 0; mt < 4; mt++) {
            int r = wm * 64 + mt * 16 + gid;
            float2 f0 = *(const float2*)&As[(size_t)r * SPAD + k2];
            float2 f1 = *(const float2*)&As[(size_t)(r + 8) * SPAD + k2];
            a[mt][0] = __float_as_uint(f0.x);
            a[mt][1] = __float_as_uint(f1.x);
            a[mt][2] = __float_as_uint(f0.y);
            a[mt][3] = __float_as_uint(f1.y);
        }
        #pragma unroll
        for (int nt = 0; nt < 4; nt++) {
            int cn = wn * 32 + nt * 8 + gid;
            float2 fb = *(const float2*)&Bs[(size_t)cn * SPAD + k2];
            #pragma unroll
            for (int mt = 0; mt < 4; mt++)
                mma_tf32(c[mt][nt], a[mt],
                         __float_as_uint(fb.x), __float_as_uint(fb.y));
        }
    }
}

__device__ __forceinline__ void gemm_mainloop(const float* __restrict__ A,
                                              const float* __restrict__ W,
                                              float c[4][4][4],
                                              int bm, int bn, int tid) {
    extern __shared__ float dyn[];
    uint32_t sbase;
    asm("{ .reg .u64 t; cvta.to.shared.u64 t, %1; cvt.u32.u64 %0, t; }"
        : "=r"(sbase) : "l"(dyn));

    const int lane = tid & 31, wid = tid >> 5;
    const int gid = lane >> 2, tig = lane & 3;
    const int wm = wid >> 2, wn = wid & 3;

    const int NIT = C_DIM / BK;   // 32

    issue_stage(sbase, sbase + (uint32_t)(STAGE_F * 4), A, W, bm, bn, 0, tid);
    CP_COMMIT();

    for (int i = 0; i < NIT; i++) {
        CP_WAIT0();
        __syncthreads();

        int nxt = i + 1;
        if (nxt < NIT) {
            uint32_t s_a = sbase + (uint32_t)((nxt & 1) * 2 * STAGE_F * 4);
            uint32_t s_b = s_a + (uint32_t)(STAGE_F * 4);
            issue_stage(s_a, s_b, A, W, bm, bn, nxt * BK, tid);
        }
        CP_COMMIT();

        const float* As = dyn + (size_t)(i & 1) * 2 * STAGE_F;
        const float* Bs = As + STAGE_F;
        tile_mma4(As, Bs, c, wm, wn, gid, tig);
    }
}

// QKV fused. Epilogue: Q scaled(0.125*log2e)+rounded+permuted, K rounded+
// permuted, V rounded natural — attention mainloop needs zero cvt.
__global__ __launch_bounds__(256, 2) void gemm_qkv_kernel()
{
    const int z = blockIdx.z;
    const float* W = g_wc[z];
    float* dst     = (z == 0) ? g_q : (z == 1) ? g_k : g_v;
    const float scale = (z == 0) ? QSCALE : 1.0f;

    const int tid = threadIdx.x;
    const int lane = tid & 31, wid = tid >> 5;
    const int gid = lane >> 2, tig = lane & 3;
    const int wm = wid >> 2, wn = wid & 3;
    const int bm = blockIdx.y * BM, bn = blockIdx.x * BN;

    float c[4][4][4];
    #pragma unroll
    for (int mt = 0; mt < 4; mt++)
        #pragma unroll
        for (int nt = 0; nt < 4; nt++)
            #pragma unroll
            for (int i = 0; i < 4; i++) c[mt][nt][i] = 0.f;

    gemm_mainloop(g_xc, W, c, bm, bn, tid);

    #pragma unroll
    for (int mt = 0; mt < 4; mt++)
        #pragma unroll
        for (int nt = 0; nt < 4; nt++) {
            int row0 = bm + wm * 64 + mt * 16 + gid;
            int n    = bn + wn * 32 + nt * 8 + tig * 2;
            int hh = n >> 6, d = n & 63;
            if (z <= 1) {
                // permuted scalar stores: pos(d), pos(d)+2 (d is even)
                int dp = (d & ~7) | ((d & 3) << 1) | ((d >> 2) & 1);
                #pragma unroll
                for (int i = 0; i < 2; i++) {
                    int m = row0 + i * 8;
                    int t = m >> 1, bb = m & 1;
                    size_t base = (((size_t)bb * H_NUM + hh) * T_SEQ + t) * D_HEAD;
                    dst[base + dp    ] = cvt_tf32(c[mt][nt][i * 2    ] * scale);
                    dst[base + dp + 2] = cvt_tf32(c[mt][nt][i * 2 + 1] * scale);
                }
            } else {
                #pragma unroll
                for (int i = 0; i < 2; i++) {
                    int m = row0 + i * 8;
                    int t = m >> 1, bb = m & 1;
                    size_t base = (((size_t)bb * H_NUM + hh) * T_SEQ + t) * D_HEAD;
                    *(float2*)&dst[base + d] =
                        make_float2(cvt_tf32(c[mt][nt][i * 2]),
                                    cvt_tf32(c[mt][nt][i * 2 + 1]));
                }
            }
        }
}

__global__ __launch_bounds__(256, 2) void gemm_out_kernel(float* __restrict__ out)
{
    const int tid = threadIdx.x;
    const int lane = tid & 31, wid = tid >> 5;
    const int gid = lane >> 2, tig = lane & 3;
    const int wm = wid >> 2, wn = wid & 3;
    const int bm = blockIdx.y * BM, bn = blockIdx.x * BN;

    float c[4][4][4];
    #pragma unroll
    for (int mt = 0; mt < 4; mt++)
        #pragma unroll
        for (int nt = 0; nt < 4; nt++)
            #pragma unroll
            for (int i = 0; i < 4; i++) c[mt][nt][i] = 0.f;

    gemm_mainloop(g_ctxp, g_wc[3], c, bm, bn, tid);

    #pragma unroll
    for (int mt = 0; mt < 4; mt++)
        #pragma unroll
        for (int nt = 0; nt < 4; nt++) {
            int row0 = bm + wm * 64 + mt * 16 + gid;
            int col0 = bn + wn * 32 + nt * 8 + tig * 2;
            *(float2*)(out + (size_t)row0 * C_DIM + col0) =
                make_float2(c[mt][nt][0], c[mt][nt][1]);
            *(float2*)(out + (size_t)(row0 + 8) * C_DIM + col0) =
                make_float2(c[mt][nt][2], c[mt][nt][3]);
        }
}

// ---------------------------------------------------------------------------
// Tensor-core causal flash attention (round-11 structure + log2 softmax):
// inputs pre-rounded (K/Q pre-permuted), cp.async double-buffered K/V
// staging, zero cvt in the loop, ex2.approx softmax. 128 threads = 4 warps.
// ---------------------------------------------------------------------------
#define AT_TILE (64 * 72)
#define AT_STAGE (2 * AT_TILE)
#define ATTN_SMEM (2 * AT_STAGE * 4)

__device__ __forceinline__ void attn_issue_kv(uint32_t sbase, int stage,
                                              const float* __restrict__ Kp,
                                              const float* __restrict__ Vp,
                                              int kb, int tid) {
    uint32_t kdst = sbase + (uint32_t)(stage * AT_STAGE * 4);
    uint32_t vdst = kdst + (uint32_t)(AT_TILE * 4);
    #pragma unroll
    for (int it = 0; it < 8; it++) {
        int idx = tid + it * 128;      // 0..1023 : 16B chunks (64 rows x 16)
        int r  = idx >> 4;             // 0..63
        int cc = (idx & 15) * 4;       // 0..60
        uint32_t off = (uint32_t)((r * 72 + cc) * 4);
        CP16(kdst + off, Kp + (size_t)(kb * 64 + r) * 64 + cc);
        CP16(vdst + off, Vp + (size_t)(kb * 64 + r) * 64 + cc);
    }
}

__global__ __launch_bounds__(128) void attn_tc_kernel()
{
    const int qb = (gridDim.x - 1) - blockIdx.x;
    const int h  = blockIdx.y;
    const int b  = blockIdx.z;
    const size_t base = (((size_t)b * H_NUM + h) * T_SEQ) * D_HEAD;
    const float* Qp = g_q + base;
    const float* Kp = g_k + base;
    const float* Vp = g_v + base;

    extern __shared__ float at_dyn[];
    uint32_t sbase;
    asm("{ .reg .u64 t; cvta.to.shared.u64 t, %1; cvt.u32.u64 %0, t; }"
        : "=r"(sbase) : "l"(at_dyn));

    const int tid  = threadIdx.x;
    const int lane = tid & 31;
    const int wid  = tid >> 5;
    const int gid  = lane >> 2;
    const int tig  = lane & 3;

    const int t0 = qb * 64 + wid * 16 + gid;
    const int t1 = t0 + 8;

    // Q a-frags: pre-scaled/rounded/permuted -> float2 loads, no math
    uint32_t qa[8][4];
    #pragma unroll
    for (int kk = 0; kk < 8; kk++) {
        float2 f0 = *(const float2*)(Qp + (size_t)t0 * 64 + kk * 8 + tig * 2);
        float2 f1 = *(const float2*)(Qp + (size_t)t1 * 64 + kk * 8 + tig * 2);
        qa[kk][0] = __float_as_uint(f0.x);
        qa[kk][1] = __float_as_uint(f1.x);
        qa[kk][2] = __float_as_uint(f0.y);
        qa[kk][3] = __float_as_uint(f1.y);
    }

    float m0 = -1e30f, m1 = -1e30f, l0 = 0.f, l1 = 0.f;
    float o[8][4];
    #pragma unroll
    for (int nt = 0; nt < 8; nt++)
        #pragma unroll
        for (int i = 0; i < 4; i++) o[nt][i] = 0.f;

    const int nkb = qb + 1;

    attn_issue_kv(sbase, 0, Kp, Vp, 0, tid);
    CP_COMMIT();

    for (int kb = 0; kb < nkb; kb++) {
        if (kb + 1 < nkb) {
            attn_issue_kv(sbase, (kb + 1) & 1, Kp, Vp, kb + 1, tid);
            CP_COMMIT();
            CP_WAIT1();
        } else {
            CP_WAIT0();
        }
        __syncthreads();

        const float* Ks = at_dyn + (size_t)(kb & 1) * AT_STAGE;
        const float* Vs = Ks + AT_TILE;

        float s[8][4];
        #pragma unroll
        for (int nt = 0; nt < 8; nt++)
            #pragma unroll
            for (int i = 0; i < 4; i++) s[nt][i] = 0.f;

        #pragma unroll
        for (int kk = 0; kk < 8; kk++) {
            #pragma unroll
            for (int nt = 0; nt < 8; nt++) {
                float2 kbf = *(const float2*)&Ks[(size_t)(nt * 8 + gid) * 72 + kk * 8 + tig * 2];
                mma_tf32(s[nt], qa[kk], __float_as_uint(kbf.x), __float_as_uint(kbf.y));
            }
        }

        if (kb == qb) {
            #pragma unroll
            for (int nt = 0; nt < 8; nt++) {
                int cg = kb * 64 + nt * 8 + tig * 2;
                if (cg     > t0) s[nt][0] = -1e30f;
                if (cg + 1 > t0) s[nt][1] = -1e30f;
                if (cg     > t1) s[nt][2] = -1e30f;
                if (cg + 1 > t1) s[nt][3] = -1e30f;
            }
        }

        float mb0 = m0, mb1 = m1;
        #pragma unroll
        for (int nt = 0; nt < 8; nt++) {
            mb0 = fmaxf(mb0, fmaxf(s[nt][0], s[nt][1]));
            mb1 = fmaxf(mb1, fmaxf(s[nt][2], s[nt][3]));
        }
        mb0 = fmaxf(mb0, __shfl_xor_sync(0xffffffffu, mb0, 1));
        mb0 = fmaxf(mb0, __shfl_xor_sync(0xffffffffu, mb0, 2));
        mb1 = fmaxf(mb1, __shfl_xor_sync(0xffffffffu, mb1, 1));
        mb1 = fmaxf(mb1, __shfl_xor_sync(0xffffffffu, mb1, 2));

        // log2-domain corrections: one MUFU each
        float corr0 = ex2f(m0 - mb0);
        float corr1 = ex2f(m1 - mb1);
        m0 = mb0; m1 = mb1;
        l0 *= corr0; l1 *= corr1;
        #pragma unroll
        for (int nt = 0; nt < 8; nt++) {
            o[nt][0] *= corr0; o[nt][1] *= corr0;
            o[nt][2] *= corr1; o[nt][3] *= corr1;
        }

        #pragma unroll
        for (int nt = 0; nt < 8; nt++) {
            s[nt][0] = ex2f(s[nt][0] - m0);
            s[nt][1] = ex2f(s[nt][1] - m0);
            s[nt][2] = ex2f(s[nt][2] - m1);
            s[nt][3] = ex2f(s[nt][3] - m1);
            l0 += s[nt][0] + s[nt][1];
            l1 += s[nt][2] + s[nt][3];
        }

        #pragma unroll
        for (int kk = 0; kk < 8; kk++) {
            int src  = (lane & ~3) | (tig >> 1);
            int src2 = src + 2;
            float v00 = __shfl_sync(0xffffffffu, s[kk][0], src);
            float v01 = __shfl_sync(0xffffffffu, s[kk][1], src);
            float v10 = __shfl_sync(0xffffffffu, s[kk][2], src);
            float v11 = __shfl_sync(0xffffffffu, s[kk][3], src);
            float w00 = __shfl_sync(0xffffffffu, s[kk][0], src2);
            float w01 = __shfl_sync(0xffffffffu, s[kk][1], src2);
            float w10 = __shfl_sync(0xffffffffu, s[kk][2], src2);
            float w11 = __shfl_sync(0xffffffffu, s[kk][3], src2);
            bool odd = (tig & 1);
            uint32_t pa[4];
            pa[0] = __float_as_uint(cvt_tf32(odd ? v01 : v00));
            pa[1] = __float_as_uint(cvt_tf32(odd ? v11 : v10));
            pa[2] = __float_as_uint(cvt_tf32(odd ? w01 : w00));
            pa[3] = __float_as_uint(cvt_tf32(odd ? w11 : w10));
            #pragma unroll
            for (int nt = 0; nt < 8; nt++) {
                uint32_t b0 = __float_as_uint(Vs[(size_t)(kk * 8 + tig    ) * 72 + nt * 8 + gid]);
                uint32_t b1 = __float_as_uint(Vs[(size_t)(kk * 8 + tig + 4) * 72 + nt * 8 + gid]);
                mma_tf32(o[nt], pa, b0, b1);
            }
        }
        __syncthreads();
    }

    l0 += __shfl_xor_sync(0xffffffffu, l0, 1);
    l0 += __shfl_xor_sync(0xffffffffu, l0, 2);
    l1 += __shfl_xor_sync(0xffffffffu, l1, 1);
    l1 += __shfl_xor_sync(0xffffffffu, l1, 2);
    float inv0 = 1.f / l0;
    float inv1 = 1.f / l1;

    // write ctx rounded + column-permuted (within groups of 8)
    const int k0 = tig * 2;
    const int p0 = ((k0 & 3) << 1) | ((k0 >> 2) & 1);
    const int p1 = (((k0 + 1) & 3) << 1) | (((k0 + 1) >> 2) & 1);
    #pragma unroll
    for (int nt = 0; nt < 8; nt++) {
        int cb = h * 64 + nt * 8;
        size_t r0 = ((size_t)t0 * B_SZ + b) * C_DIM + cb;
        size_t r1 = ((size_t)t1 * B_SZ + b) * C_DIM + cb;
        g_ctxp[r0 + p0] = cvt_tf32(o[nt][0] * inv0);
        g_ctxp[r0 + p1] = cvt_tf32(o[nt][1] * inv0);
        g_ctxp[r1 + p0] = cvt_tf32(o[nt][2] * inv1);
        g_ctxp[r1 + p1] = cvt_tf32(o[nt][3] * inv1);
    }
}

// ---------------------------------------------------------------------------
extern "C" void kernel_launch(void* const* d_in, const int* in_sizes, int n_in,
                              void* d_out, int out_size)
{
    const float* x  = (const float*)d_in[0];
    const float* Wq = (const float*)d_in[1];
    const float* Wk = (const float*)d_in[2];
    const float* Wv = (const float*)d_in[3];
    const float* Wo = (const float*)d_in[4];
    float* out = (float*)d_out;

    cudaFuncSetAttribute(gemm_qkv_kernel,
                         cudaFuncAttributeMaxDynamicSharedMemorySize, GEMM_SMEM);
    cudaFuncSetAttribute(gemm_out_kernel,
                         cudaFuncAttributeMaxDynamicSharedMemorySize, GEMM_SMEM);
    cudaFuncSetAttribute(attn_tc_kernel,
                         cudaFuncAttributeMaxDynamicSharedMemorySize, ATTN_SMEM);

    int nconv = (X_F4 + 4 * W_F4) / 256;     // 8192 blocks
    preconvert_kernel<<<nconv, 256>>>(x, Wq, Wk, Wv, Wo);

    dim3 gq(C_DIM / BN, M_ROWS / BM, 3);     // (8, 32, 3)
    gemm_qkv_kernel<<<gq, 256, GEMM_SMEM>>>();

    dim3 ga(T_SEQ / 64, H_NUM, B_SZ);        // (32, 16, 2)
    attn_tc_kernel<<<ga, 128, ATTN_SMEM>>>();

    dim3 go(C_DIM / BN, M_ROWS / BM);        // (8, 32)
    gemm_out_kernel<<<go, 256, GEMM_SMEM>>>(out);
}

// round 15
// speedup vs baseline: 1.7951x; 1.6110x over previous
#include <cuda_runtime.h>
#include <cuda_fp16.h>
#include <math.h>
#include <stdint.h>

#define T_SEQ 2048
#define B_SZ  2
#define C_DIM 1024
#define H_NUM 16
#define D_HEAD 64
#define M_ROWS (T_SEQ * B_SZ)   // 4096

// All fp16, fp32 accumulation in mma. Pair-permute within 16-half groups:
// pair p=k>>1 -> word pos wp = ((p&3)<<1)|(p>>2), so fragment (k,k+1,k+8,k+9)
// quads are contiguous (one LDS.64).
// g_q16: (B,H,T,D) scaled by 0.125*log2e, pair-permuted d
// g_k16: (B,H,T,D) pair-permuted d ; g_v16: (B,H,T,D) natural d
__device__ uint16_t g_q16[(size_t)B_SZ * H_NUM * T_SEQ * D_HEAD];
__device__ uint16_t g_k16[(size_t)B_SZ * H_NUM * T_SEQ * D_HEAD];
__device__ uint16_t g_v16[(size_t)B_SZ * H_NUM * T_SEQ * D_HEAD];
__device__ uint16_t g_xc16[(size_t)M_ROWS * C_DIM];      // x fp16, pair-permuted
__device__ uint16_t g_wc16[4][(size_t)C_DIM * C_DIM];    // weights fp16, permuted
__device__ uint16_t g_ctx16[(size_t)M_ROWS * C_DIM];     // ctx fp16, permuted

#define QSCALE 0.18033688f   // 0.125 * log2(e)

__device__ __forceinline__ float ex2f(float x) {
    float r;
    asm("ex2.approx.f32 %0, %1;" : "=f"(r) : "f"(x));
    return r;
}

// pack (lo, hi) floats -> fp16x2 in one instr
#define PACKH2(d, lo, hi) \
    asm("cvt.rn.f16x2.f32 %0, %1, %2;" : "=r"(d) : "f"(hi), "f"(lo))

__device__ __forceinline__ void mma_f16(float c[4], const uint32_t a[4],
                                        uint32_t b0, uint32_t b1) {
    asm volatile(
        "mma.sync.aligned.m16n8k16.row.col.f32.f16.f16.f32 "
        "{%0,%1,%2,%3}, {%4,%5,%6,%7}, {%8,%9}, {%0,%1,%2,%3};"
        : "+f"(c[0]), "+f"(c[1]), "+f"(c[2]), "+f"(c[3])
        : "r"(a[0]), "r"(a[1]), "r"(a[2]), "r"(a[3]), "r"(b0), "r"(b1));
}

#define CP16(dst_u32, src_ptr) \
    asm volatile("cp.async.cg.shared.global [%0], [%1], 16;" \
                 :: "r"(dst_u32), "l"(src_ptr))
#define CP_COMMIT() asm volatile("cp.async.commit_group;" ::: "memory")
#define CP_WAIT0()  asm volatile("cp.async.wait_group 0;" ::: "memory")
#define CP_WAIT1()  asm volatile("cp.async.wait_group 1;" ::: "memory")

// ---------------------------------------------------------------------------
// Pre-convert fp32 -> fp16 with pair permute.
// ---------------------------------------------------------------------------
#define X_F4 (M_ROWS * C_DIM / 4)   // 1048576
#define W_F4 (C_DIM * C_DIM / 4)    // 262144

__global__ __launch_bounds__(256) void preconvert_kernel(
    const float* __restrict__ x,  const float* __restrict__ Wq,
    const float* __restrict__ Wk, const float* __restrict__ Wv,
    const float* __restrict__ Wo)
{
    int g = blockIdx.x * 256 + threadIdx.x;
    const float* src;
    uint16_t* dst;
    int off;
    if (g < X_F4) {
        src = x; dst = g_xc16; off = g;
    } else {
        int r = g - X_F4;
        int t = r / W_F4;
        off = r - t * W_F4;
        src = (t == 0) ? Wq : (t == 1) ? Wk : (t == 2) ? Wv : Wo;
        dst = g_wc16[t];
    }
    float4 v = ((const float4*)src)[off];
    int fi  = off * 4;
    int kg  = fi & 15;               // 0,4,8,12
    int bse = fi - kg;
    int p0  = kg >> 1;               // 0,2,4,6
    int wp0 = ((p0 & 3) << 1) | (p0 >> 2);
    int p1  = p0 + 1;
    int wp1 = ((p1 & 3) << 1) | (p1 >> 2);
    uint32_t h0, h1;
    PACKH2(h0, v.x, v.y);
    PACKH2(h1, v.z, v.w);
    *(uint32_t*)(dst + bse + 2 * wp0) = h0;
    *(uint32_t*)(dst + bse + 2 * wp1) = h1;
}

// ---------------------------------------------------------------------------
// FP16 NT GEMM: CTA 128x128, BKH=64 halves, 256 threads (8 warps 2x4),
// warp 64x32 via m16n8k16. SPADH=72 halves (conflict-free LDS.64).
// 2-stage cp.async. smem = 2*2*128*72*2 = 73728 B -> 2 CTAs/SM.
// ---------------------------------------------------------------------------
#define BM 128
#define BN 128
#define BKH 64
#define SPADH 72
#define STAGE_H (BM * SPADH)                // halves per tile
#define GEMM_SMEM (2 * 2 * STAGE_H * 2)     // 73728 bytes

__device__ __forceinline__ void issue_stage(uint32_t s_a, uint32_t s_b,
                                            const uint16_t* __restrict__ A,
                                            const uint16_t* __restrict__ W,
                                            int bm, int bn, int k0, int tid) {
    #pragma unroll
    for (int i = 0; i < 4; i++) {
        int idx = tid + i * 256;            // 0..1023
        int r   = idx >> 3;                 // 0..127
        int cb  = (idx & 7) * 16;           // byte offset in 128B row
        CP16(s_a + (uint32_t)(r * (SPADH * 2) + cb),
             (const char*)(A + (size_t)(bm + r) * C_DIM + k0) + cb);
    }
    #pragma unroll
    for (int i = 0; i < 4; i++) {
        int idx = tid + i * 256;
        int r   = idx >> 3;
        int cb  = (idx & 7) * 16;
        CP16(s_b + (uint32_t)(r * (SPADH * 2) + cb),
             (const char*)(W + (size_t)(bn + r) * C_DIM + k0) + cb);
    }
}

__device__ __forceinline__ void tile_mma_f16(const uint16_t* __restrict__ As,
                                             const uint16_t* __restrict__ Bs,
                                             float c[4][4][4],
                                             int wm, int wn, int gid, int tig) {
    #pragma unroll
    for (int kk = 0; kk < 4; kk++) {        // 4 k16 slabs in BKH=64
        const int ho = kk * 16 + 4 * tig;
        uint32_t a[4][4];
        #pragma unroll
        for (int mt = 0; mt < 4; mt++) {
            int r = wm * 64 + mt * 16 + gid;
            uint2 a02 = *(const uint2*)(As + (size_t)r * SPADH + ho);
            uint2 a13 = *(const uint2*)(As + (size_t)(r + 8) * SPADH + ho);
            a[mt][0] = a02.x; a[mt][1] = a13.x;
            a[mt][2] = a02.y; a[mt][3] = a13.y;
        }
        #pragma unroll
        for (int nt = 0; nt < 4; nt++) {
            int cn = wn * 32 + nt * 8 + gid;
            uint2 b01 = *(const uint2*)(Bs + (size_t)cn * SPADH + ho);
            #pragma unroll
            for (int mt = 0; mt < 4; mt++)
                mma_f16(c[mt][nt], a[mt], b01.x, b01.y);
        }
    }
}

__device__ __forceinline__ void gemm_mainloop(const uint16_t* __restrict__ A,
                                              const uint16_t* __restrict__ W,
                                              float c[4][4][4],
                                              int bm, int bn, int tid) {
    extern __shared__ uint16_t dynh[];
    uint32_t sbase;
    asm("{ .reg .u64 t; cvta.to.shared.u64 t, %1; cvt.u32.u64 %0, t; }"
        : "=r"(sbase) : "l"(dynh));

    const int lane = tid & 31, wid = tid >> 5;
    const int gid = lane >> 2, tig = lane & 3;
    const int wm = wid >> 2, wn = wid & 3;

    const int NIT = C_DIM / BKH;   // 16

    issue_stage(sbase, sbase + (uint32_t)(STAGE_H * 2), A, W, bm, bn, 0, tid);
    CP_COMMIT();

    for (int i = 0; i < NIT; i++) {
        CP_WAIT0();
        __syncthreads();

        int nxt = i + 1;
        if (nxt < NIT) {
            uint32_t s_a = sbase + (uint32_t)((nxt & 1) * 2 * STAGE_H * 2);
            uint32_t s_b = s_a + (uint32_t)(STAGE_H * 2);
            issue_stage(s_a, s_b, A, W, bm, bn, nxt * BKH, tid);
        }
        CP_COMMIT();

        const uint16_t* As = dynh + (size_t)(i & 1) * 2 * STAGE_H;
        const uint16_t* Bs = As + STAGE_H;
        tile_mma_f16(As, Bs, c, wm, wn, gid, tig);
    }
}

// QKV fused: Q scaled+permuted, K permuted, V natural (all fp16, B,H,T,D).
__global__ __launch_bounds__(256, 2) void gemm_qkv_kernel()
{
    const int z = blockIdx.z;
    const uint16_t* W = g_wc16[z];
    uint16_t* dst = (z == 0) ? g_q16 : (z == 1) ? g_k16 : g_v16;
    const float scale = (z == 0) ? QSCALE : 1.0f;

    const int tid = threadIdx.x;
    const int lane = tid & 31, wid = tid >> 5;
    const int gid = lane >> 2, tig = lane & 3;
    const int wm = wid >> 2, wn = wid & 3;
    const int bm = blockIdx.y * BM, bn = blockIdx.x * BN;

    float c[4][4][4];
    #pragma unroll
    for (int mt = 0; mt < 4; mt++)
        #pragma unroll
        for (int nt = 0; nt < 4; nt++)
            #pragma unroll
            for (int i = 0; i < 4; i++) c[mt][nt][i] = 0.f;

    gemm_mainloop(g_xc16, W, c, bm, bn, tid);

    #pragma unroll
    for (int mt = 0; mt < 4; mt++)
        #pragma unroll
        for (int nt = 0; nt < 4; nt++) {
            int row0 = bm + wm * 64 + mt * 16 + gid;
            int n    = bn + wn * 32 + nt * 8 + tig * 2;
            int hh = n >> 6, d = n & 63;
            // pair-permuted offset for Q/K; natural for V
            int wp   = 2 * tig + (nt & 1);
            int hoff = (z <= 1) ? ((d & ~15) + 2 * wp) : d;
            #pragma unroll
            for (int i = 0; i < 2; i++) {
                int m = row0 + i * 8;
                int t = m >> 1, bb = m & 1;
                size_t base = (((size_t)bb * H_NUM + hh) * T_SEQ + t) * D_HEAD;
                uint32_t hv;
                PACKH2(hv, c[mt][nt][i * 2] * scale, c[mt][nt][i * 2 + 1] * scale);
                *(uint32_t*)(dst + base + hoff) = hv;
            }
        }
}

__global__ __launch_bounds__(256, 2) void gemm_out_kernel(float* __restrict__ out)
{
    const int tid = threadIdx.x;
    const int lane = tid & 31, wid = tid >> 5;
    const int gid = lane >> 2, tig = lane & 3;
    const int wm = wid >> 2, wn = wid & 3;
    const int bm = blockIdx.y * BM, bn = blockIdx.x * BN;

    float c[4][4][4];
    #pragma unroll
    for (int mt = 0; mt < 4; mt++)
        #pragma unroll
        for (int nt = 0; nt < 4; nt++)
            #pragma unroll
            for (int i = 0; i < 4; i++) c[mt][nt][i] = 0.f;

    gemm_mainloop(g_ctx16, g_wc16[3], c, bm, bn, tid);

    #pragma unroll
    for (int mt = 0; mt < 4; mt++)
        #pragma unroll
        for (int nt = 0; nt < 4; nt++) {
            int row0 = bm + wm * 64 + mt * 16 + gid;
            int col0 = bn + wn * 32 + nt * 8 + tig * 2;
            *(float2*)(out + (size_t)row0 * C_DIM + col0) =
                make_float2(c[mt][nt][0], c[mt][nt][1]);
            *(float2*)(out + (size_t)(row0 + 8) * C_DIM + col0) =
                make_float2(c[mt][nt][2], c[mt][nt][3]);
        }
}

// ---------------------------------------------------------------------------
// FP16 causal flash attention: m16n8k16, log2 softmax (ex2.approx),
// P->a-frag via cvt packs (NO shuffles), V b-frags via ldmatrix.x4.trans.
// 128 threads = 4 warps, Q-tile 64, K/V fp16 tiles 64x72 halves.
// smem = 2 stages * 2 * 64*72*2 = 36864 B -> 4 CTAs/SM.
// ---------------------------------------------------------------------------
#define AT_TILE_H (64 * SPADH)          // halves per K (or V) tile
#define AT_STAGE_H (2 * AT_TILE_H)
#define ATTN_SMEM (2 * AT_STAGE_H * 2)  // 36864 bytes

__device__ __forceinline__ void attn_issue_kv(uint32_t sbase, int stage,
                                              const uint16_t* __restrict__ Kp,
                                              const uint16_t* __restrict__ Vp,
                                              int kb, int tid) {
    uint32_t kdst = sbase + (uint32_t)(stage * AT_STAGE_H * 2);
    uint32_t vdst = kdst + (uint32_t)(AT_TILE_H * 2);
    #pragma unroll
    for (int it = 0; it < 4; it++) {
        int idx = tid + it * 128;      // 0..511 : 16B chunks (64 rows x 8)
        int r  = idx >> 3;             // 0..63
        int cb = (idx & 7) * 16;       // 0..112 bytes (row = 128B of halves)
        uint32_t off = (uint32_t)(r * (SPADH * 2) + cb);
        CP16(kdst + off, (const char*)(Kp + (size_t)(kb * 64 + r) * 64) + cb);
        CP16(vdst + off, (const char*)(Vp + (size_t)(kb * 64 + r) * 64) + cb);
    }
}

__global__ __launch_bounds__(128) void attn_tc_kernel()
{
    const int qb = (gridDim.x - 1) - blockIdx.x;
    const int h  = blockIdx.y;
    const int b  = blockIdx.z;
    const size_t base = (((size_t)b * H_NUM + h) * T_SEQ) * D_HEAD;
    const uint16_t* Qp = g_q16 + base;
    const uint16_t* Kp = g_k16 + base;
    const uint16_t* Vp = g_v16 + base;

    extern __shared__ uint16_t at_dynh[];
    uint32_t sbase;
    asm("{ .reg .u64 t; cvta.to.shared.u64 t, %1; cvt.u32.u64 %0, t; }"
        : "=r"(sbase) : "l"(at_dynh));

    const int tid  = threadIdx.x;
    const int lane = tid & 31;
    const int wid  = tid >> 5;
    const int gid  = lane >> 2;
    const int tig  = lane & 3;

    const int t0 = qb * 64 + wid * 16 + gid;
    const int t1 = t0 + 8;

    // Q a-frags: D=64 -> 4 k16 slabs, pair-permuted gmem -> uint2 loads
    uint32_t qa[4][4];
    #pragma unroll
    for (int kk = 0; kk < 4; kk++) {
        uint2 q02 = *(const uint2*)(Qp + (size_t)t0 * 64 + kk * 16 + 4 * tig);
        uint2 q13 = *(const uint2*)(Qp + (size_t)t1 * 64 + kk * 16 + 4 * tig);
        qa[kk][0] = q02.x; qa[kk][1] = q13.x;
        qa[kk][2] = q02.y; qa[kk][3] = q13.y;
    }

    float m0 = -1e30f, m1 = -1e30f, l0 = 0.f, l1 = 0.f;
    float o[8][4];
    #pragma unroll
    for (int nt = 0; nt < 8; nt++)
        #pragma unroll
        for (int i = 0; i < 4; i++) o[nt][i] = 0.f;

    const int nkb = qb + 1;

    attn_issue_kv(sbase, 0, Kp, Vp, 0, tid);
    CP_COMMIT();

    for (int kb = 0; kb < nkb; kb++) {
        if (kb + 1 < nkb) {
            attn_issue_kv(sbase, (kb + 1) & 1, Kp, Vp, kb + 1, tid);
            CP_COMMIT();
            CP_WAIT1();
        } else {
            CP_WAIT0();
        }
        __syncthreads();

        const uint16_t* Ks = at_dynh + (size_t)(kb & 1) * AT_STAGE_H;
        uint32_t vs_base = sbase + (uint32_t)((kb & 1) * AT_STAGE_H * 2)
                                 + (uint32_t)(AT_TILE_H * 2);

        // S = Q @ K^T (K natural rows=kv, permuted d pairs -> LDS.64 b-frags)
        float s[8][4];
        #pragma unroll
        for (int nt = 0; nt < 8; nt++)
            #pragma unroll
            for (int i = 0; i < 4; i++) s[nt][i] = 0.f;

        #pragma unroll
        for (int kk = 0; kk < 4; kk++) {
            const int ho = kk * 16 + 4 * tig;
            #pragma unroll
            for (int nt = 0; nt < 8; nt++) {
                uint2 b01 = *(const uint2*)(Ks + (size_t)(nt * 8 + gid) * SPADH + ho);
                mma_f16(s[nt], qa[kk], b01.x, b01.y);
            }
        }

        if (kb == qb) {
            #pragma unroll
            for (int nt = 0; nt < 8; nt++) {
                int cg = kb * 64 + nt * 8 + tig * 2;
                if (cg     > t0) s[nt][0] = -1e30f;
                if (cg + 1 > t0) s[nt][1] = -1e30f;
                if (cg     > t1) s[nt][2] = -1e30f;
                if (cg + 1 > t1) s[nt][3] = -1e30f;
            }
        }

        float mb0 = m0, mb1 = m1;
        #pragma unroll
        for (int nt = 0; nt < 8; nt++) {
            mb0 = fmaxf(mb0, fmaxf(s[nt][0], s[nt][1]));
            mb1 = fmaxf(mb1, fmaxf(s[nt][2], s[nt][3]));
        }
        mb0 = fmaxf(mb0, __shfl_xor_sync(0xffffffffu, mb0, 1));
        mb0 = fmaxf(mb0, __shfl_xor_sync(0xffffffffu, mb0, 2));
        mb1 = fmaxf(mb1, __shfl_xor_sync(0xffffffffu, mb1, 1));
        mb1 = fmaxf(mb1, __shfl_xor_sync(0xffffffffu, mb1, 2));

        float corr0 = ex2f(m0 - mb0);
        float corr1 = ex2f(m1 - mb1);
        m0 = mb0; m1 = mb1;
        l0 *= corr0; l1 *= corr1;
        #pragma unroll
        for (int nt = 0; nt < 8; nt++) {
            o[nt][0] *= corr0; o[nt][1] *= corr0;
            o[nt][2] *= corr1; o[nt][3] *= corr1;
        }

        #pragma unroll
        for (int nt = 0; nt < 8; nt++) {
            s[nt][0] = ex2f(s[nt][0] - m0);
            s[nt][1] = ex2f(s[nt][1] - m0);
            s[nt][2] = ex2f(s[nt][2] - m1);
            s[nt][3] = ex2f(s[nt][3] - m1);
            l0 += s[nt][0] + s[nt][1];
            l1 += s[nt][2] + s[nt][3];
        }

        // O += P @ V : P a-frags = local cvt packs (no shuffles);
        // V b-frags via ldmatrix.x4.trans on natural-layout V tile.
        #pragma unroll
        for (int s4 = 0; s4 < 4; s4++) {       // k16 slab over kv rows
            uint32_t pa[4];
            PACKH2(pa[0], s[2 * s4    ][0], s[2 * s4    ][1]);
            PACKH2(pa[1], s[2 * s4    ][2], s[2 * s4    ][3]);
            PACKH2(pa[2], s[2 * s4 + 1][0], s[2 * s4 + 1][1]);
            PACKH2(pa[3], s[2 * s4 + 1][2], s[2 * s4 + 1][3]);
            const int mi = lane >> 3, lr = lane & 7;
            #pragma unroll
            for (int ntp = 0; ntp < 4; ntp++) { // d-group of 16
                uint32_t addr = vs_base +
                    (uint32_t)(((s4 * 16 + (mi & 1) * 8 + lr) * SPADH
                                + ntp * 16 + (mi >> 1) * 8) * 2);
                uint32_t r0, r1, r2, r3;
                asm volatile(
                    "ldmatrix.sync.aligned.m8n8.x4.trans.shared.b16 "
                    "{%0,%1,%2,%3}, [%4];"
                    : "=r"(r0), "=r"(r1), "=r"(r2), "=r"(r3) : "r"(addr));
                mma_f16(o[2 * ntp    ], pa, r0, r1);
                mma_f16(o[2 * ntp + 1], pa, r2, r3);
            }
        }
        __syncthreads();
    }

    l0 += __shfl_xor_sync(0xffffffffu, l0, 1);
    l0 += __shfl_xor_sync(0xffffffffu, l0, 2);
    l1 += __shfl_xor_sync(0xffffffffu, l1, 1);
    l1 += __shfl_xor_sync(0xffffffffu, l1, 2);
    float inv0 = 1.f / l0;
    float inv1 = 1.f / l1;

    // ctx: fp16, pair-permuted cols (consumed by fp16 out-proj GEMM)
    #pragma unroll
    for (int nt = 0; nt < 8; nt++) {
        int col  = h * 64 + nt * 8 + tig * 2;
        int wp   = 2 * tig + (nt & 1);
        int hoff = (col & ~15) + 2 * wp;
        size_t r0 = ((size_t)t0 * B_SZ + b) * C_DIM + (col & ~63) - (col & ~63) + 0;
        // row bases (full C_DIM rows)
        size_t rb0 = ((size_t)t0 * B_SZ + b) * C_DIM;
        size_t rb1 = ((size_t)t1 * B_SZ + b) * C_DIM;
        (void)r0;
        int gb = (col & ~15);          // group base within row
        uint32_t h0, h1;
        PACKH2(h0, o[nt][0] * inv0, o[nt][1] * inv0);
        PACKH2(h1, o[nt][2] * inv1, o[nt][3] * inv1);
        *(uint32_t*)(g_ctx16 + rb0 + gb + (hoff - gb)) = h0;
        *(uint32_t*)(g_ctx16 + rb1 + gb + (hoff - gb)) = h1;
    }
}

// ---------------------------------------------------------------------------
extern "C" void kernel_launch(void* const* d_in, const int* in_sizes, int n_in,
                              void* d_out, int out_size)
{
    const float* x  = (const float*)d_in[0];
    const float* Wq = (const float*)d_in[1];
    const float* Wk = (const float*)d_in[2];
    const float* Wv = (const float*)d_in[3];
    const float* Wo = (const float*)d_in[4];
    float* out = (float*)d_out;

    cudaFuncSetAttribute(gemm_qkv_kernel,
                         cudaFuncAttributeMaxDynamicSharedMemorySize, GEMM_SMEM);
    cudaFuncSetAttribute(gemm_out_kernel,
                         cudaFuncAttributeMaxDynamicSharedMemorySize, GEMM_SMEM);
    cudaFuncSetAttribute(attn_tc_kernel,
                         cudaFuncAttributeMaxDynamicSharedMemorySize, ATTN_SMEM);

    int nconv = (X_F4 + 4 * W_F4) / 256;     // 8192 blocks
    preconvert_kernel<<<nconv, 256>>>(x, Wq, Wk, Wv, Wo);

    dim3 gq(C_DIM / BN, M_ROWS / BM, 3);     // (8, 32, 3)
    gemm_qkv_kernel<<<gq, 256, GEMM_SMEM>>>();

    dim3 ga(T_SEQ / 64, H_NUM, B_SZ);        // (32, 16, 2)
    attn_tc_kernel<<<ga, 128, ATTN_SMEM>>>();

    dim3 go(C_DIM / BN, M_ROWS / BM);        // (8, 32)
    gemm_out_kernel<<<go, 256, GEMM_SMEM>>>(out);
}

// round 16
// speedup vs baseline: 2.1383x; 1.1912x over previous
#include <cuda_runtime.h>
#include <cuda_fp16.h>
#include <math.h>
#include <stdint.h>

#define T_SEQ 2048
#define B_SZ  2
#define C_DIM 1024
#define H_NUM 16
#define D_HEAD 64
#define M_ROWS (T_SEQ * B_SZ)   // 4096

// All fp16, fp32 accumulation in mma. Pair-permute within 16-half groups:
// pair p=k>>1 -> word pos wp = ((p&3)<<1)|(p>>2), so fragment (k,k+1,k+8,k+9)
// quads are contiguous (one LDS.64).
// g_q16: (B,H,T,D) scaled by 0.125*log2e, pair-permuted d
// g_k16: (B,H,T,D) pair-permuted d ; g_v16: (B,H,T,D) natural d
__device__ uint16_t g_q16[(size_t)B_SZ * H_NUM * T_SEQ * D_HEAD];
__device__ uint16_t g_k16[(size_t)B_SZ * H_NUM * T_SEQ * D_HEAD];
__device__ uint16_t g_v16[(size_t)B_SZ * H_NUM * T_SEQ * D_HEAD];
__device__ uint16_t g_xc16[(size_t)M_ROWS * C_DIM];      // x fp16, pair-permuted
__device__ uint16_t g_wc16[4][(size_t)C_DIM * C_DIM];    // weights fp16, permuted
__device__ uint16_t g_ctx16[(size_t)M_ROWS * C_DIM];     // ctx fp16, permuted

#define QSCALE 0.18033688f   // 0.125 * log2(e)

__device__ __forceinline__ float ex2f(float x) {
    float r;
    asm("ex2.approx.f32 %0, %1;" : "=f"(r) : "f"(x));
    return r;
}

// pack (lo, hi) floats -> fp16x2 in one instr
#define PACKH2(d, lo, hi) \
    asm("cvt.rn.f16x2.f32 %0, %1, %2;" : "=r"(d) : "f"(hi), "f"(lo))

__device__ __forceinline__ void mma_f16(float c[4], const uint32_t a[4],
                                        uint32_t b0, uint32_t b1) {
    asm volatile(
        "mma.sync.aligned.m16n8k16.row.col.f32.f16.f16.f32 "
        "{%0,%1,%2,%3}, {%4,%5,%6,%7}, {%8,%9}, {%0,%1,%2,%3};"
        : "+f"(c[0]), "+f"(c[1]), "+f"(c[2]), "+f"(c[3])
        : "r"(a[0]), "r"(a[1]), "r"(a[2]), "r"(a[3]), "r"(b0), "r"(b1));
}

#define CP16(dst_u32, src_ptr) \
    asm volatile("cp.async.cg.shared.global [%0], [%1], 16;" \
                 :: "r"(dst_u32), "l"(src_ptr))
#define CP_COMMIT() asm volatile("cp.async.commit_group;" ::: "memory")
#define CP_WAIT0()  asm volatile("cp.async.wait_group 0;" ::: "memory")
#define CP_WAIT1()  asm volatile("cp.async.wait_group 1;" ::: "memory")

// ---------------------------------------------------------------------------
// Pre-convert fp32 -> fp16 with pair permute.
// ---------------------------------------------------------------------------
#define X_F4 (M_ROWS * C_DIM / 4)   // 1048576
#define W_F4 (C_DIM * C_DIM / 4)    // 262144

__global__ __launch_bounds__(256) void preconvert_kernel(
    const float* __restrict__ x,  const float* __restrict__ Wq,
    const float* __restrict__ Wk, const float* __restrict__ Wv,
    const float* __restrict__ Wo)
{
    int g = blockIdx.x * 256 + threadIdx.x;
    const float* src;
    uint16_t* dst;
    int off;
    if (g < X_F4) {
        src = x; dst = g_xc16; off = g;
    } else {
        int r = g - X_F4;
        int t = r / W_F4;
        off = r - t * W_F4;
        src = (t == 0) ? Wq : (t == 1) ? Wk : (t == 2) ? Wv : Wo;
        dst = g_wc16[t];
    }
    float4 v = ((const float4*)src)[off];
    int fi  = off * 4;
    int kg  = fi & 15;               // 0,4,8,12
    int bse = fi - kg;
    int p0  = kg >> 1;               // 0,2,4,6
    int wp0 = ((p0 & 3) << 1) | (p0 >> 2);
    int p1  = p0 + 1;
    int wp1 = ((p1 & 3) << 1) | (p1 >> 2);
    uint32_t h0, h1;
    PACKH2(h0, v.x, v.y);
    PACKH2(h1, v.z, v.w);
    *(uint32_t*)(dst + bse + 2 * wp0) = h0;
    *(uint32_t*)(dst + bse + 2 * wp1) = h1;
}

// ---------------------------------------------------------------------------
// FP16 NT GEMM: CTA 128x128, BKH=64 halves, 256 threads (8 warps 2x4),
// warp 64x32 via m16n8k16. SPADH=80 halves: stride 160B = 40 words = 8 mod 32
// banks -> conflict-free LDS.64 fragment loads (fp16-correct re-derivation).
// 2-stage cp.async. smem = 2*2*128*80*2 = 81920 B -> 2 CTAs/SM.
// ---------------------------------------------------------------------------
#define BM 128
#define BN 128
#define BKH 64
#define SPADH 80
#define STAGE_H (BM * SPADH)                // halves per tile
#define GEMM_SMEM (2 * 2 * STAGE_H * 2)     // 81920 bytes

__device__ __forceinline__ void issue_stage(uint32_t s_a, uint32_t s_b,
                                            const uint16_t* __restrict__ A,
                                            const uint16_t* __restrict__ W,
                                            int bm, int bn, int k0, int tid) {
    #pragma unroll
    for (int i = 0; i < 4; i++) {
        int idx = tid + i * 256;            // 0..1023
        int r   = idx >> 3;                 // 0..127
        int cb  = (idx & 7) * 16;           // byte offset in 128B row
        CP16(s_a + (uint32_t)(r * (SPADH * 2) + cb),
             (const char*)(A + (size_t)(bm + r) * C_DIM + k0) + cb);
    }
    #pragma unroll
    for (int i = 0; i < 4; i++) {
        int idx = tid + i * 256;
        int r   = idx >> 3;
        int cb  = (idx & 7) * 16;
        CP16(s_b + (uint32_t)(r * (SPADH * 2) + cb),
             (const char*)(W + (size_t)(bn + r) * C_DIM + k0) + cb);
    }
}

__device__ __forceinline__ void tile_mma_f16(const uint16_t* __restrict__ As,
                                             const uint16_t* __restrict__ Bs,
                                             float c[4][4][4],
                                             int wm, int wn, int gid, int tig) {
    #pragma unroll
    for (int kk = 0; kk < 4; kk++) {        // 4 k16 slabs in BKH=64
        const int ho = kk * 16 + 4 * tig;
        uint32_t a[4][4];
        #pragma unroll
        for (int mt = 0; mt < 4; mt++) {
            int r = wm * 64 + mt * 16 + gid;
            uint2 a02 = *(const uint2*)(As + (size_t)r * SPADH + ho);
            uint2 a13 = *(const uint2*)(As + (size_t)(r + 8) * SPADH + ho);
            a[mt][0] = a02.x; a[mt][1] = a13.x;
            a[mt][2] = a02.y; a[mt][3] = a13.y;
        }
        #pragma unroll
        for (int nt = 0; nt < 4; nt++) {
            int cn = wn * 32 + nt * 8 + gid;
            uint2 b01 = *(const uint2*)(Bs + (size_t)cn * SPADH + ho);
            #pragma unroll
            for (int mt = 0; mt < 4; mt++)
                mma_f16(c[mt][nt], a[mt], b01.x, b01.y);
        }
    }
}

__device__ __forceinline__ void gemm_mainloop(const uint16_t* __restrict__ A,
                                              const uint16_t* __restrict__ W,
                                              float c[4][4][4],
                                              int bm, int bn, int tid) {
    extern __shared__ uint16_t dynh[];
    uint32_t sbase;
    asm("{ .reg .u64 t; cvta.to.shared.u64 t, %1; cvt.u32.u64 %0, t; }"
        : "=r"(sbase) : "l"(dynh));

    const int lane = tid & 31, wid = tid >> 5;
    const int gid = lane >> 2, tig = lane & 3;
    const int wm = wid >> 2, wn = wid & 3;

    const int NIT = C_DIM / BKH;   // 16

    issue_stage(sbase, sbase + (uint32_t)(STAGE_H * 2), A, W, bm, bn, 0, tid);
    CP_COMMIT();

    for (int i = 0; i < NIT; i++) {
        CP_WAIT0();
        __syncthreads();

        int nxt = i + 1;
        if (nxt < NIT) {
            uint32_t s_a = sbase + (uint32_t)((nxt & 1) * 2 * STAGE_H * 2);
            uint32_t s_b = s_a + (uint32_t)(STAGE_H * 2);
            issue_stage(s_a, s_b, A, W, bm, bn, nxt * BKH, tid);
        }
        CP_COMMIT();

        const uint16_t* As = dynh + (size_t)(i & 1) * 2 * STAGE_H;
        const uint16_t* Bs = As + STAGE_H;
        tile_mma_f16(As, Bs, c, wm, wn, gid, tig);
    }
}

// QKV fused: Q scaled+permuted, K permuted, V natural (all fp16, B,H,T,D).
__global__ __launch_bounds__(256, 2) void gemm_qkv_kernel()
{
    const int z = blockIdx.z;
    const uint16_t* W = g_wc16[z];
    uint16_t* dst = (z == 0) ? g_q16 : (z == 1) ? g_k16 : g_v16;
    const float scale = (z == 0) ? QSCALE : 1.0f;

    const int tid = threadIdx.x;
    const int lane = tid & 31, wid = tid >> 5;
    const int gid = lane >> 2, tig = lane & 3;
    const int wm = wid >> 2, wn = wid & 3;
    const int bm = blockIdx.y * BM, bn = blockIdx.x * BN;

    float c[4][4][4];
    #pragma unroll
    for (int mt = 0; mt < 4; mt++)
        #pragma unroll
        for (int nt = 0; nt < 4; nt++)
            #pragma unroll
            for (int i = 0; i < 4; i++) c[mt][nt][i] = 0.f;

    gemm_mainloop(g_xc16, W, c, bm, bn, tid);

    #pragma unroll
    for (int mt = 0; mt < 4; mt++)
        #pragma unroll
        for (int nt = 0; nt < 4; nt++) {
            int row0 = bm + wm * 64 + mt * 16 + gid;
            int n    = bn + wn * 32 + nt * 8 + tig * 2;
            int hh = n >> 6, d = n & 63;
            // pair-permuted offset for Q/K; natural for V
            int wp   = 2 * tig + (nt & 1);
            int hoff = (z <= 1) ? ((d & ~15) + 2 * wp) : d;
            #pragma unroll
            for (int i = 0; i < 2; i++) {
                int m = row0 + i * 8;
                int t = m >> 1, bb = m & 1;
                size_t base = (((size_t)bb * H_NUM + hh) * T_SEQ + t) * D_HEAD;
                uint32_t hv;
                PACKH2(hv, c[mt][nt][i * 2] * scale, c[mt][nt][i * 2 + 1] * scale);
                *(uint32_t*)(dst + base + hoff) = hv;
            }
        }
}

__global__ __launch_bounds__(256, 2) void gemm_out_kernel(float* __restrict__ out)
{
    const int tid = threadIdx.x;
    const int lane = tid & 31, wid = tid >> 5;
    const int gid = lane >> 2, tig = lane & 3;
    const int wm = wid >> 2, wn = wid & 3;
    const int bm = blockIdx.y * BM, bn = blockIdx.x * BN;

    float c[4][4][4];
    #pragma unroll
    for (int mt = 0; mt < 4; mt++)
        #pragma unroll
        for (int nt = 0; nt < 4; nt++)
            #pragma unroll
            for (int i = 0; i < 4; i++) c[mt][nt][i] = 0.f;

    gemm_mainloop(g_ctx16, g_wc16[3], c, bm, bn, tid);

    #pragma unroll
    for (int mt = 0; mt < 4; mt++)
        #pragma unroll
        for (int nt = 0; nt < 4; nt++) {
            int row0 = bm + wm * 64 + mt * 16 + gid;
            int col0 = bn + wn * 32 + nt * 8 + tig * 2;
            *(float2*)(out + (size_t)row0 * C_DIM + col0) =
                make_float2(c[mt][nt][0], c[mt][nt][1]);
            *(float2*)(out + (size_t)(row0 + 8) * C_DIM + col0) =
                make_float2(c[mt][nt][2], c[mt][nt][3]);
        }
}

// ---------------------------------------------------------------------------
// FP16 causal flash attention: m16n8k16, log2 softmax (ex2.approx),
// P->a-frag via cvt packs (NO shuffles), V b-frags via ldmatrix.x4.trans.
// 128 threads = 4 warps, Q-tile 64, K/V fp16 tiles 64x80 halves.
// smem = 2 stages * 2 * 64*80*2 = 40960 B.
// ---------------------------------------------------------------------------
#define AT_TILE_H (64 * SPADH)          // halves per K (or V) tile
#define AT_STAGE_H (2 * AT_TILE_H)
#define ATTN_SMEM (2 * AT_STAGE_H * 2)  // 40960 bytes

__device__ __forceinline__ void attn_issue_kv(uint32_t sbase, int stage,
                                              const uint16_t* __restrict__ Kp,
                                              const uint16_t* __restrict__ Vp,
                                              int kb, int tid) {
    uint32_t kdst = sbase + (uint32_t)(stage * AT_STAGE_H * 2);
    uint32_t vdst = kdst + (uint32_t)(AT_TILE_H * 2);
    #pragma unroll
    for (int it = 0; it < 4; it++) {
        int idx = tid + it * 128;      // 0..511 : 16B chunks (64 rows x 8)
        int r  = idx >> 3;             // 0..63
        int cb = (idx & 7) * 16;       // 0..112 bytes (row = 128B of halves)
        uint32_t off = (uint32_t)(r * (SPADH * 2) + cb);
        CP16(kdst + off, (const char*)(Kp + (size_t)(kb * 64 + r) * 64) + cb);
        CP16(vdst + off, (const char*)(Vp + (size_t)(kb * 64 + r) * 64) + cb);
    }
}

__global__ __launch_bounds__(128) void attn_tc_kernel()
{
    const int qb = (gridDim.x - 1) - blockIdx.x;
    const int h  = blockIdx.y;
    const int b  = blockIdx.z;
    const size_t base = (((size_t)b * H_NUM + h) * T_SEQ) * D_HEAD;
    const uint16_t* Qp = g_q16 + base;
    const uint16_t* Kp = g_k16 + base;
    const uint16_t* Vp = g_v16 + base;

    extern __shared__ uint16_t at_dynh[];
    uint32_t sbase;
    asm("{ .reg .u64 t; cvta.to.shared.u64 t, %1; cvt.u32.u64 %0, t; }"
        : "=r"(sbase) : "l"(at_dynh));

    const int tid  = threadIdx.x;
    const int lane = tid & 31;
    const int wid  = tid >> 5;
    const int gid  = lane >> 2;
    const int tig  = lane & 3;

    const int t0 = qb * 64 + wid * 16 + gid;
    const int t1 = t0 + 8;

    // Q a-frags: D=64 -> 4 k16 slabs, pair-permuted gmem -> uint2 loads
    uint32_t qa[4][4];
    #pragma unroll
    for (int kk = 0; kk < 4; kk++) {
        uint2 q02 = *(const uint2*)(Qp + (size_t)t0 * 64 + kk * 16 + 4 * tig);
        uint2 q13 = *(const uint2*)(Qp + (size_t)t1 * 64 + kk * 16 + 4 * tig);
        qa[kk][0] = q02.x; qa[kk][1] = q13.x;
        qa[kk][2] = q02.y; qa[kk][3] = q13.y;
    }

    float m0 = -1e30f, m1 = -1e30f, l0 = 0.f, l1 = 0.f;
    float o[8][4];
    #pragma unroll
    for (int nt = 0; nt < 8; nt++)
        #pragma unroll
        for (int i = 0; i < 4; i++) o[nt][i] = 0.f;

    const int nkb = qb + 1;

    attn_issue_kv(sbase, 0, Kp, Vp, 0, tid);
    CP_COMMIT();

    for (int kb = 0; kb < nkb; kb++) {
        if (kb + 1 < nkb) {
            attn_issue_kv(sbase, (kb + 1) & 1, Kp, Vp, kb + 1, tid);
            CP_COMMIT();
            CP_WAIT1();
        } else {
            CP_WAIT0();
        }
        __syncthreads();

        const uint16_t* Ks = at_dynh + (size_t)(kb & 1) * AT_STAGE_H;
        uint32_t vs_base = sbase + (uint32_t)((kb & 1) * AT_STAGE_H * 2)
                                 + (uint32_t)(AT_TILE_H * 2);

        // S = Q @ K^T (K natural rows=kv, permuted d pairs -> LDS.64 b-frags)
        float s[8][4];
        #pragma unroll
        for (int nt = 0; nt < 8; nt++)
            #pragma unroll
            for (int i = 0; i < 4; i++) s[nt][i] = 0.f;

        #pragma unroll
        for (int kk = 0; kk < 4; kk++) {
            const int ho = kk * 16 + 4 * tig;
            #pragma unroll
            for (int nt = 0; nt < 8; nt++) {
                uint2 b01 = *(const uint2*)(Ks + (size_t)(nt * 8 + gid) * SPADH + ho);
                mma_f16(s[nt], qa[kk], b01.x, b01.y);
            }
        }

        if (kb == qb) {
            #pragma unroll
            for (int nt = 0; nt < 8; nt++) {
                int cg = kb * 64 + nt * 8 + tig * 2;
                if (cg     > t0) s[nt][0] = -1e30f;
                if (cg + 1 > t0) s[nt][1] = -1e30f;
                if (cg     > t1) s[nt][2] = -1e30f;
                if (cg + 1 > t1) s[nt][3] = -1e30f;
            }
        }

        float mb0 = m0, mb1 = m1;
        #pragma unroll
        for (int nt = 0; nt < 8; nt++) {
            mb0 = fmaxf(mb0, fmaxf(s[nt][0], s[nt][1]));
            mb1 = fmaxf(mb1, fmaxf(s[nt][2], s[nt][3]));
        }
        mb0 = fmaxf(mb0, __shfl_xor_sync(0xffffffffu, mb0, 1));
        mb0 = fmaxf(mb0, __shfl_xor_sync(0xffffffffu, mb0, 2));
        mb1 = fmaxf(mb1, __shfl_xor_sync(0xffffffffu, mb1, 1));
        mb1 = fmaxf(mb1, __shfl_xor_sync(0xffffffffu, mb1, 2));

        float corr0 = ex2f(m0 - mb0);
        float corr1 = ex2f(m1 - mb1);
        m0 = mb0; m1 = mb1;
        l0 *= corr0; l1 *= corr1;
        #pragma unroll
        for (int nt = 0; nt < 8; nt++) {
            o[nt][0] *= corr0; o[nt][1] *= corr0;
            o[nt][2] *= corr1; o[nt][3] *= corr1;
        }

        #pragma unroll
        for (int nt = 0; nt < 8; nt++) {
            s[nt][0] = ex2f(s[nt][0] - m0);
            s[nt][1] = ex2f(s[nt][1] - m0);
            s[nt][2] = ex2f(s[nt][2] - m1);
            s[nt][3] = ex2f(s[nt][3] - m1);
            l0 += s[nt][0] + s[nt][1];
            l1 += s[nt][2] + s[nt][3];
        }

        // O += P @ V : P a-frags = local cvt packs (no shuffles);
        // V b-frags via ldmatrix.x4.trans on natural-layout V tile.
        #pragma unroll
        for (int s4 = 0; s4 < 4; s4++) {       // k16 slab over kv rows
            uint32_t pa[4];
            PACKH2(pa[0], s[2 * s4    ][0], s[2 * s4    ][1]);
            PACKH2(pa[1], s[2 * s4    ][2], s[2 * s4    ][3]);
            PACKH2(pa[2], s[2 * s4 + 1][0], s[2 * s4 + 1][1]);
            PACKH2(pa[3], s[2 * s4 + 1][2], s[2 * s4 + 1][3]);
            const int mi = lane >> 3, lr = lane & 7;
            #pragma unroll
            for (int ntp = 0; ntp < 4; ntp++) { // d-group of 16
                uint32_t addr = vs_base +
                    (uint32_t)(((s4 * 16 + (mi & 1) * 8 + lr) * SPADH
                                + ntp * 16 + (mi >> 1) * 8) * 2);
                uint32_t r0, r1, r2, r3;
                asm volatile(
                    "ldmatrix.sync.aligned.m8n8.x4.trans.shared.b16 "
                    "{%0,%1,%2,%3}, [%4];"
                    : "=r"(r0), "=r"(r1), "=r"(r2), "=r"(r3) : "r"(addr));
                mma_f16(o[2 * ntp    ], pa, r0, r1);
                mma_f16(o[2 * ntp + 1], pa, r2, r3);
            }
        }
        __syncthreads();
    }

    l0 += __shfl_xor_sync(0xffffffffu, l0, 1);
    l0 += __shfl_xor_sync(0xffffffffu, l0, 2);
    l1 += __shfl_xor_sync(0xffffffffu, l1, 1);
    l1 += __shfl_xor_sync(0xffffffffu, l1, 2);
    float inv0 = 1.f / l0;
    float inv1 = 1.f / l1;

    // ctx: fp16, pair-permuted cols (consumed by fp16 out-proj GEMM)
    #pragma unroll
    for (int nt = 0; nt < 8; nt++) {
        int col  = h * 64 + nt * 8 + tig * 2;
        int wp   = 2 * tig + (nt & 1);
        int gb   = (col & ~15);
        int hoff = gb + 2 * wp;
        size_t rb0 = ((size_t)t0 * B_SZ + b) * C_DIM;
        size_t rb1 = ((size_t)t1 * B_SZ + b) * C_DIM;
        uint32_t h0, h1;
        PACKH2(h0, o[nt][0] * inv0, o[nt][1] * inv0);
        PACKH2(h1, o[nt][2] * inv1, o[nt][3] * inv1);
        *(uint32_t*)(g_ctx16 + rb0 + hoff) = h0;
        *(uint32_t*)(g_ctx16 + rb1 + hoff) = h1;
    }
}

// ---------------------------------------------------------------------------
extern "C" void kernel_launch(void* const* d_in, const int* in_sizes, int n_in,
                              void* d_out, int out_size)
{
    const float* x  = (const float*)d_in[0];
    const float* Wq = (const float*)d_in[1];
    const float* Wk = (const float*)d_in[2];
    const float* Wv = (const float*)d_in[3];
    const float* Wo = (const float*)d_in[4];
    float* out = (float*)d_out;

    cudaFuncSetAttribute(gemm_qkv_kernel,
                         cudaFuncAttributeMaxDynamicSharedMemorySize, GEMM_SMEM);
    cudaFuncSetAttribute(gemm_out_kernel,
                         cudaFuncAttributeMaxDynamicSharedMemorySize, GEMM_SMEM);
    cudaFuncSetAttribute(attn_tc_kernel,
                         cudaFuncAttributeMaxDynamicSharedMemorySize, ATTN_SMEM);

    int nconv = (X_F4 + 4 * W_F4) / 256;     // 8192 blocks
    preconvert_kernel<<<nconv, 256>>>(x, Wq, Wk, Wv, Wo);

    dim3 gq(C_DIM / BN, M_ROWS / BM, 3);     // (8, 32, 3)
    gemm_qkv_kernel<<<gq, 256, GEMM_SMEM>>>();

    dim3 ga(T_SEQ / 64, H_NUM, B_SZ);        // (32, 16, 2)
    attn_tc_kernel<<<ga, 128, ATTN_SMEM>>>();

    dim3 go(C_DIM / BN, M_ROWS / BM);        // (8, 32)
    gemm_out_kernel<<<go, 256, GEMM_SMEM>>>(out);
}